// round 13
// baseline (speedup 1.0000x reference)
#include <cuda_runtime.h>
#include <math.h>

#define NSd   12
#define NCd   4
#define Td    32
#define NZd   512
#define NEQ   384
#define NIN   128
#define DAMPv 1e-4f
#define LS    17
#define MS    272          // 16*17 floats per matrix
#define NTHR  256

struct Smem {
    float M[256];          // [A|B] 12x16, rows 12-15 zero, stride 16
    float MtM[256];
    float E[MS];           // -rho*[M;0], stride 17 (rebuilt per factorization)
    float x0[12];
    float z[NZd], Qd[NZd], cd[NZd], g[NZd];
    float lamE[NEQ], lamU[NIN], lamL[NIN], lo[NIN], up[NIN];
    float Yv[NEQ];
    float D [32 * MS];     // diag blocks -> inverses of eliminated blocks
    float Bl[32 * MS];     // Dinv*C (left coupling)
    float Br[32 * MS];     // Dinv*C_next^T (right coupling)
    float CA[16 * MS];     // coupling buffers (ping-pong across levels)
    float CB[8 * MS];
    int   act[NIN];
};

__device__ __forceinline__ float buildD(const Smem* S, int t, int i, int j, float rho) {
    float v = (t < Td - 1) ? rho * S->MtM[i * 16 + j] : 0.f;
    if (i == j) {
        v += S->Qd[t * 16 + i] + DAMPv;
        if (i < 12) v += rho;
        else {
            int a = S->act[t * 4 + (i - 12)];
            if (a & 1) v += rho;
            if (a & 2) v += rho;
        }
    }
    return v;
}

// split-lane GJ with 2x2 block pivots; stride-LS in/out; in-place safe
__device__ __forceinline__ void gj16b(const float* Psrc, float* dst, int lane) {
    const int r  = lane & 15;
    const int h  = (lane >> 4) & 1;
    const int c0 = h << 3;
    float a[8];
    #pragma unroll
    for (int j = 0; j < 8; ++j) a[j] = Psrc[r * LS + c0 + j];
    #pragma unroll
    for (int kb = 0; kb < 8; ++kb) {
        const int p  = 2 * kb, q = p + 1;
        const int kh = p >> 3;
        const int pc = p & 7, qc = q & 7;
        float bpp = __shfl_sync(0xffffffffu, a[pc], p + (kh << 4));
        float bpq = __shfl_sync(0xffffffffu, a[qc], p + (kh << 4));
        float bqp = __shfl_sync(0xffffffffu, a[pc], q + (kh << 4));
        float bqq = __shfl_sync(0xffffffffu, a[qc], q + (kh << 4));
        float idet = __fdividef(1.0f, bpp * bqq - bpq * bqp);
        float i00 =  bqq * idet, i01 = -bpq * idet;
        float i10 = -bqp * idet, i11 =  bpp * idet;
        float f0 = __shfl_sync(0xffffffffu, a[pc], r + (kh << 4));
        float f1 = __shfl_sync(0xffffffffu, a[qc], r + (kh << 4));
        float g0 = f0 * i00 + f1 * i10;
        float g1 = f0 * i01 + f1 * i11;
        const bool isp = (r == p), isq = (r == q);
        #pragma unroll
        for (int j = 0; j < 8; ++j) {
            float R0 = __shfl_sync(0xffffffffu, a[j], p + (h << 4));
            float R1 = __shfl_sync(0xffffffffu, a[j], q + (h << 4));
            float np  = i00 * R0 + i01 * R1;
            float nq  = i10 * R0 + i11 * R1;
            float upd = a[j] - g0 * R0 - g1 * R1;
            a[j] = isp ? np : (isq ? nq : upd);
        }
        if (h == kh) {
            a[pc] = isp ? i00 : (isq ? i10 : -g0);
            a[qc] = isp ? i01 : (isq ? i11 : -g1);
        }
    }
    #pragma unroll
    for (int j = 0; j < 8; ++j) dst[r * LS + c0 + j] = a[j];
}

__device__ __forceinline__ const float* Cread(const Smem* S, int lv, int j) {
    if (lv == 0) return S->E;                      // all level-0 couplings == E
    return (lv & 1) ? &S->CA[j * MS] : &S->CB[j * MS];
}
__device__ __forceinline__ float* Cwrite(Smem* S, int lv, int m) {
    return (lv & 1) ? &S->CB[m * MS] : &S->CA[m * MS];
}

__global__ __launch_bounds__(NTHR, 1)
void mpc_kernel(const float* __restrict__ x0g, const float* __restrict__ Qg,
                const float* __restrict__ cg,  const float* __restrict__ Ag,
                const float* __restrict__ Bg,  const float* __restrict__ log_,
                const float* __restrict__ upg, float* __restrict__ out, int NB)
{
    extern __shared__ float smraw[];
    Smem* S = reinterpret_cast<Smem*>(smraw);
    const int b    = blockIdx.x;
    const int tid  = threadIdx.x;
    const int wid  = tid >> 5;
    const int lane = tid & 31;

    // ---------------- load inputs ----------------
    for (int i = tid; i < NZd; i += NTHR) {
        S->z[i]  = 0.f;
        S->Qd[i] = Qg[b * NZd + i];
        S->cd[i] = cg[b * NZd + i];
    }
    for (int i = tid; i < NEQ; i += NTHR) S->lamE[i] = 0.f;
    for (int i = tid; i < NIN; i += NTHR) {
        S->lamU[i] = 0.f; S->lamL[i] = 0.f;
        S->lo[i]  = log_[b * NIN + i];
        S->up[i]  = upg[b * NIN + i];
        S->act[i] = -1;
    }
    for (int i = tid; i < 256; i += NTHR) {
        int r = i >> 4, cc = i & 15;
        float mv = 0.f;
        if (r < 12) mv = (cc < 12) ? Ag[r * 12 + cc] : Bg[r * 4 + (cc - 12)];
        S->M[i] = mv;
    }
    if (tid < 12) S->x0[tid] = x0g[b * 12 + tid];
    __syncthreads();

    // ---------------- MtM ----------------
    {
        int ri = tid >> 4, rj = tid & 15;
        float a = 0.f;
        #pragma unroll
        for (int k = 0; k < 12; ++k) a += S->M[k * 16 + ri] * S->M[k * 16 + rj];
        S->MtM[tid] = a;
    }

    // ---------------- initial rollout (warp 0) ----------------
    if (tid < 32) {
        if (tid < 12) S->z[tid] = S->x0[tid];
        for (int t = 0; t < Td - 1; ++t) {
            __syncwarp();
            if (tid < 12) {
                float acc = 0.f;
                #pragma unroll
                for (int j = 0; j < 12; ++j) acc += S->M[tid * 16 + j] * S->z[t * 16 + j];
                S->z[(t + 1) * 16 + tid] = acc;
            }
        }
    }
    __syncthreads();

    float rho = 1.f;
    for (int al = 0; al < 3; ++al) {
        for (int nt = 0; nt < 3; ++nt) {
            // ---- Yv = rho*r + lamE ----
            for (int idx = tid; idx < NEQ; idx += NTHR) {
                int t = idx / 12, i = idx % 12;
                float r;
                if (t == 0) r = S->z[i] - S->x0[i];
                else {
                    float acc = S->z[t * 16 + i];
                    const float* zp = &S->z[(t - 1) * 16];
                    const float* Mr = &S->M[i * 16];
                    #pragma unroll
                    for (int k = 0; k < 16; ++k) acc -= Mr[k] * zp[k];
                    r = acc;
                }
                S->Yv[idx] = rho * r + S->lamE[idx];
            }
            __syncthreads();
            // ---- gradient + active-set change detection ----
            int myChanged = 0;
            for (int idx = tid; idx < NZd; idx += NTHR) {
                int t = idx >> 4, i = idx & 15;
                float gv = S->Qd[idx] * S->z[idx] + S->cd[idx];
                if (i < 12) gv += S->Yv[t * 12 + i];
                if (t < Td - 1) {
                    const float* Yn = &S->Yv[(t + 1) * 12];
                    float acc = 0.f;
                    #pragma unroll
                    for (int k = 0; k < 12; ++k) acc += S->M[k * 16 + i] * Yn[k];
                    gv -= acc;
                }
                if (i >= 12) {
                    int u = t * 4 + (i - 12);
                    float su = fmaxf(rho * (S->z[idx] - S->up[u]) + S->lamU[u], 0.f);
                    float sl = fmaxf(rho * (S->lo[u] - S->z[idx]) + S->lamL[u], 0.f);
                    gv += su - sl;
                    int a = (su > 0.f ? 1 : 0) | (sl > 0.f ? 2 : 0);
                    if (a != S->act[u]) { myChanged = 1; S->act[u] = a; }
                }
                S->g[idx] = gv;
            }
            int anyChanged = __syncthreads_or(myChanged);
            bool needFactor = (nt == 0) || anyChanged;
            if (!needFactor) continue;   // unchanged active set: dz ~ roundoff

            // ================= cyclic-reduction factorization =================
            // build E and all 32 diagonal blocks
            if (tid < 256) {
                int i = tid >> 4, c = tid & 15;
                S->E[i * LS + c] = (i < 12) ? -rho * S->M[i * 16 + c] : 0.f;
            }
            for (int idx = tid; idx < 32 * 256; idx += NTHR) {
                int t = idx >> 8, e = idx & 255, i = e >> 4, c = e & 15;
                S->D[t * MS + i * LS + c] = buildD(S, t, i, c, rho);
            }
            __syncthreads();

            for (int lv = 0; lv < 5; ++lv) {
                const int step = 1 << lv, n = 32 >> lv, n2 = n >> 1;
                // phase A: invert eliminated blocks (independent; warp-parallel)
                for (int m = wid; m < n2; m += 8) {
                    int t = (2 * m + 1) * step;
                    gj16b(&S->D[t * MS], &S->D[t * MS], lane);
                }
                __syncthreads();
                // phase B: Bl = Dinv*C_j, Br = Dinv*C_{j+1}^T
                for (int idx = tid; idx < n2 * 512; idx += NTHR) {
                    int m = idx >> 9, which = (idx >> 8) & 1, e = idx & 255;
                    int i = e >> 4, c = e & 15;
                    int t = (2 * m + 1) * step;
                    const float* Dv = &S->D[t * MS + i * LS];
                    if (which == 0) {
                        const float* C = Cread(S, lv, 2 * m + 1);
                        float a0 = 0.f, a1 = 0.f;
                        #pragma unroll
                        for (int k = 0; k < 16; k += 2) {
                            a0 += Dv[k]     * C[k * LS + c];
                            a1 += Dv[k + 1] * C[(k + 1) * LS + c];
                        }
                        S->Bl[t * MS + i * LS + c] = a0 + a1;
                    } else {
                        if (m == n2 - 1) { S->Br[t * MS + i * LS + c] = 0.f; }
                        else {
                            const float* C = Cread(S, lv, 2 * m + 2);
                            float a0 = 0.f, a1 = 0.f;
                            #pragma unroll
                            for (int k = 0; k < 16; k += 2) {
                                a0 += Dv[k]     * C[c * LS + k];
                                a1 += Dv[k + 1] * C[c * LS + k + 1];
                            }
                            S->Br[t * MS + i * LS + c] = a0 + a1;
                        }
                    }
                }
                __syncthreads();
                // phase C: survivor D updates + next-level couplings
                int total = n2 * 256 + (n2 - 1) * 256;
                for (int idx = tid; idx < total; idx += NTHR) {
                    if (idx < n2 * 256) {
                        int m = idx >> 8, e = idx & 255, i = e >> 4, c = e & 15;
                        int te = 2 * m * step;
                        float acc = 0.f;
                        if (m >= 1) {
                            int tl = te - step;
                            const float* C  = Cread(S, lv, 2 * m);
                            const float* Bv = &S->Br[tl * MS];
                            #pragma unroll
                            for (int k = 0; k < 16; ++k) acc += C[i * LS + k] * Bv[k * LS + c];
                        }
                        {
                            int tr = te + step;
                            const float* C  = Cread(S, lv, 2 * m + 1);
                            const float* Bv = &S->Bl[tr * MS];
                            #pragma unroll
                            for (int k = 0; k < 16; ++k) acc += C[k * LS + i] * Bv[k * LS + c];
                        }
                        S->D[te * MS + i * LS + c] -= acc;
                    } else {
                        int r2 = idx - n2 * 256;
                        int m = 1 + (r2 >> 8), e = r2 & 255, i = e >> 4, c = e & 15;
                        int tl = (2 * m - 1) * step;
                        const float* C  = Cread(S, lv, 2 * m);
                        const float* Bv = &S->Bl[tl * MS];
                        float acc = 0.f;
                        #pragma unroll
                        for (int k = 0; k < 16; ++k) acc += C[i * LS + k] * Bv[k * LS + c];
                        Cwrite(S, lv, m)[i * LS + c] = -acc;
                    }
                }
                __syncthreads();
            }
            if (wid == 0) gj16b(&S->D[0], &S->D[0], lane);   // final block
            __syncthreads();

            // ================= solve H dz = g (CR down/up) =================
            // down: reduce RHS at survivors
            for (int lv = 0; lv < 5; ++lv) {
                const int step = 1 << lv, n = 32 >> lv, n2 = n >> 1;
                for (int idx = tid; idx < n2 * 16; idx += NTHR) {
                    int m = idx >> 4, i = idx & 15;
                    int te = 2 * m * step;
                    float acc = 0.f;
                    if (m >= 1) {
                        int tl = te - step;
                        const float* Bv = &S->Br[tl * MS];
                        const float* gv = &S->g[tl * 16];
                        #pragma unroll
                        for (int k = 0; k < 16; ++k) acc += Bv[k * LS + i] * gv[k];
                    }
                    {
                        int tr = te + step;
                        const float* Bv = &S->Bl[tr * MS];
                        const float* gv = &S->g[tr * 16];
                        #pragma unroll
                        for (int k = 0; k < 16; ++k) acc += Bv[k * LS + i] * gv[k];
                    }
                    S->g[te * 16 + i] -= acc;
                }
                __syncthreads();
            }
            // top: x0 = Dinv[0] * g[0]
            {
                float topv = 0.f;
                if (tid < 16) {
                    const float* Dv = &S->D[tid * LS];
                    #pragma unroll
                    for (int k = 0; k < 16; ++k) topv += Dv[k] * S->g[k];
                }
                __syncthreads();
                if (tid < 16) S->g[tid] = topv;
                __syncthreads();
            }
            // up: recover eliminated blocks
            for (int lv = 4; lv >= 0; --lv) {
                const int step = 1 << lv, n = 32 >> lv, n2 = n >> 1;
                float val = 0.f; int tj = 0, i = 0; bool actv = (tid < n2 * 16);
                if (actv) {
                    int m = tid >> 4; i = tid & 15;
                    tj = (2 * m + 1) * step;
                    const float* Dv = &S->D [tj * MS + i * LS];
                    const float* Bv = &S->Bl[tj * MS + i * LS];
                    const float* gj = &S->g[tj * 16];
                    const float* xl = &S->g[(tj - step) * 16];
                    float acc = 0.f;
                    #pragma unroll
                    for (int k = 0; k < 16; ++k) acc += Dv[k] * gj[k] - Bv[k] * xl[k];
                    if (m < n2 - 1) {
                        const float* Rv = &S->Br[tj * MS + i * LS];
                        const float* xr = &S->g[(tj + step) * 16];
                        #pragma unroll
                        for (int k = 0; k < 16; ++k) acc -= Rv[k] * xr[k];
                    }
                    val = acc;
                }
                __syncthreads();
                if (actv) S->g[tj * 16 + i] = val;
                __syncthreads();
            }
            // ---- z -= dz ----
            for (int idx = tid; idx < NZd; idx += NTHR) S->z[idx] -= S->g[idx];
            __syncthreads();
        } // newton

        // ---- multiplier updates ----
        for (int idx = tid; idx < NEQ; idx += NTHR) {
            int t = idx / 12, i = idx % 12;
            float r;
            if (t == 0) r = S->z[i] - S->x0[i];
            else {
                float acc = S->z[t * 16 + i];
                const float* zp = &S->z[(t - 1) * 16];
                const float* Mr = &S->M[i * 16];
                #pragma unroll
                for (int k = 0; k < 16; ++k) acc -= Mr[k] * zp[k];
                r = acc;
            }
            S->lamE[idx] += rho * r;
        }
        for (int idx = tid; idx < NIN; idx += NTHR) {
            int t = idx >> 2, j = idx & 3;
            float uv = S->z[t * 16 + 12 + j];
            S->lamU[idx] = fmaxf(S->lamU[idx] + rho * (uv - S->up[idx]), 0.f);
            S->lamL[idx] = fmaxf(S->lamL[idx] + rho * (S->lo[idx] - uv), 0.f);
        }
        __syncthreads();
        rho = fminf(rho * 10.f, 100.f);
    } // al

    // ---------------- outputs: x [NB,T,NS] then u [NB,T,NC] ----------------
    for (int idx = tid; idx < NEQ; idx += NTHR) {
        int t = idx / 12, i = idx % 12;
        out[b * (Td * NSd) + idx] = S->z[t * 16 + i];
    }
    for (int idx = tid; idx < NIN; idx += NTHR) {
        int t = idx >> 2, j = idx & 3;
        out[NB * (Td * NSd) + b * (Td * NCd) + idx] = S->z[t * 16 + 12 + j];
    }
}

extern "C" void kernel_launch(void* const* d_in, const int* in_sizes, int n_in,
                              void* d_out, int out_size)
{
    const float* x0 = (const float*)d_in[0];
    const float* Q  = (const float*)d_in[1];
    const float* c  = (const float*)d_in[2];
    const float* A  = (const float*)d_in[3];
    const float* B  = (const float*)d_in[4];
    const float* lo = (const float*)d_in[5];
    const float* up = (const float*)d_in[6];
    float* out = (float*)d_out;

    int NB = in_sizes[0] / NSd;   // 64
    size_t smem = sizeof(Smem);
    cudaFuncSetAttribute(mpc_kernel, cudaFuncAttributeMaxDynamicSharedMemorySize, (int)smem);
    mpc_kernel<<<NB, NTHR, smem>>>(x0, Q, c, A, B, lo, up, out, NB);
}

// round 15
// speedup vs baseline: 1.1583x; 1.1583x over previous
#include <cuda_runtime.h>
#include <math.h>

#define NSd   12
#define NCd   4
#define Td    32
#define NZd   512
#define NEQ   384
#define NIN   128
#define DAMPv 1e-4f
#define LS    17
#define MS    272          // 16*17 floats per matrix
#define NTHR  128

struct Smem {
    float M[256];          // [A|B] 12x16, rows 12-15 zero, stride 16
    float MtM[256];
    float x0[12];
    float z[NZd], Qd[NZd], cd[NZd], g[NZd], Pw[NZd];
    float lamE[NEQ], lamU[NIN], lamL[NIN], lo[NIN], up[NIN];
    float Yv[NEQ];
    float D [32 * MS];     // diag blocks; after GJ holds their inverses (in place)
    float Uf[17 * MS];     // Uf[t] = rho*M*Dinv_{t-1}, rows>=12 zero
    float Ub[31 * MS];     // Ub[t] = rho*M^T*S*Dinv_{t+1}
    int   act[NIN];
    int   fmin, fmax;
};

__device__ __forceinline__ float buildD(const Smem* S, int t, int i, int j, float rho) {
    float v = (t < Td - 1) ? rho * S->MtM[i * 16 + j] : 0.f;
    if (i == j) {
        v += S->Qd[t * 16 + i] + DAMPv;
        if (i < 12) v += rho;
        else {
            int a = S->act[t * 4 + (i - 12)];
            if (a & 1) v += rho;
            if (a & 2) v += rho;
        }
    }
    return v;
}

// split-lane GJ with 2x2 block pivots; in-place safe (reads complete first)
__device__ __forceinline__ void gj16b(float* P, int lane) {
    const int r  = lane & 15;
    const int h  = (lane >> 4) & 1;
    const int c0 = h << 3;
    float a[8];
    #pragma unroll
    for (int j = 0; j < 8; ++j) a[j] = P[r * LS + c0 + j];
    #pragma unroll
    for (int kb = 0; kb < 8; ++kb) {
        const int p  = 2 * kb, q = p + 1;
        const int kh = p >> 3;
        const int pc = p & 7, qc = q & 7;
        float bpp = __shfl_sync(0xffffffffu, a[pc], p + (kh << 4));
        float bpq = __shfl_sync(0xffffffffu, a[qc], p + (kh << 4));
        float bqp = __shfl_sync(0xffffffffu, a[pc], q + (kh << 4));
        float bqq = __shfl_sync(0xffffffffu, a[qc], q + (kh << 4));
        float idet = __fdividef(1.0f, bpp * bqq - bpq * bqp);
        float i00 =  bqq * idet, i01 = -bpq * idet;
        float i10 = -bqp * idet, i11 =  bpp * idet;
        float f0 = __shfl_sync(0xffffffffu, a[pc], r + (kh << 4));
        float f1 = __shfl_sync(0xffffffffu, a[qc], r + (kh << 4));
        float g0 = f0 * i00 + f1 * i10;
        float g1 = f0 * i01 + f1 * i11;
        const bool isp = (r == p), isq = (r == q);
        #pragma unroll
        for (int j = 0; j < 8; ++j) {
            float R0 = __shfl_sync(0xffffffffu, a[j], p + (h << 4));
            float R1 = __shfl_sync(0xffffffffu, a[j], q + (h << 4));
            float np  = i00 * R0 + i01 * R1;
            float nq  = i10 * R0 + i11 * R1;
            float upd = a[j] - g0 * R0 - g1 * R1;
            a[j] = isp ? np : (isq ? nq : upd);
        }
        if (h == kh) {
            a[pc] = isp ? i00 : (isq ? i10 : -g0);
            a[qc] = isp ? i01 : (isq ? i11 : -g1);
        }
    }
    #pragma unroll
    for (int j = 0; j < 8; ++j) P[r * LS + c0 + j] = a[j];
}

__global__ __launch_bounds__(NTHR, 1)
void mpc_kernel(const float* __restrict__ x0g, const float* __restrict__ Qg,
                const float* __restrict__ cg,  const float* __restrict__ Ag,
                const float* __restrict__ Bg,  const float* __restrict__ log_,
                const float* __restrict__ upg, float* __restrict__ out, int NB)
{
    extern __shared__ float smraw[];
    Smem* S = reinterpret_cast<Smem*>(smraw);
    const int b    = blockIdx.x;
    const int tid  = threadIdx.x;
    const int wid  = tid >> 5;
    const int lane = tid & 31;

    // ---------------- load inputs ----------------
    for (int i = tid; i < NZd; i += NTHR) {
        S->z[i]  = 0.f;
        S->Qd[i] = Qg[b * NZd + i];
        S->cd[i] = cg[b * NZd + i];
    }
    for (int i = tid; i < NEQ; i += NTHR) S->lamE[i] = 0.f;
    for (int i = tid; i < NIN; i += NTHR) {
        S->lamU[i] = 0.f; S->lamL[i] = 0.f;
        S->lo[i]  = log_[b * NIN + i];
        S->up[i]  = upg[b * NIN + i];
        S->act[i] = -1;
    }
    for (int i = tid; i < 256; i += NTHR) {
        int r = i >> 4, cc = i & 15;
        float mv = 0.f;
        if (r < 12) mv = (cc < 12) ? Ag[r * 12 + cc] : Bg[r * 4 + (cc - 12)];
        S->M[i] = mv;
    }
    if (tid < 12) S->x0[tid] = x0g[b * 12 + tid];
    __syncthreads();

    // ---------------- MtM ----------------
    for (int e = tid; e < 256; e += NTHR) {
        int ri = e >> 4, rj = e & 15;
        float a = 0.f;
        #pragma unroll
        for (int k = 0; k < 12; ++k) a += S->M[k * 16 + ri] * S->M[k * 16 + rj];
        S->MtM[e] = a;
    }

    // ---------------- initial rollout (warp 0) ----------------
    if (tid < 32) {
        if (tid < 12) S->z[tid] = S->x0[tid];
        for (int t = 0; t < Td - 1; ++t) {
            __syncwarp();
            if (tid < 12) {
                float acc = 0.f;
                #pragma unroll
                for (int j = 0; j < 12; ++j) acc += S->M[tid * 16 + j] * S->z[t * 16 + j];
                S->z[(t + 1) * 16 + tid] = acc;
            }
        }
    }
    __syncthreads();

    float rho = 1.f;
    for (int al = 0; al < 3; ++al) {
        for (int nt = 0; nt < 3; ++nt) {
            // ---- Yv = rho*r + lamE ----
            if (tid == 0) { S->fmin = 32; S->fmax = -1; }
            for (int idx = tid; idx < NEQ; idx += NTHR) {
                int t = idx / 12, i = idx % 12;
                float r;
                if (t == 0) r = S->z[i] - S->x0[i];
                else {
                    float acc = S->z[t * 16 + i];
                    const float* zp = &S->z[(t - 1) * 16];
                    const float* Mr = &S->M[i * 16];
                    #pragma unroll
                    for (int k = 0; k < 16; ++k) acc -= Mr[k] * zp[k];
                    r = acc;
                }
                S->Yv[idx] = rho * r + S->lamE[idx];
            }
            __syncthreads();
            // ---- gradient + active-set flip tracking ----
            for (int idx = tid; idx < NZd; idx += NTHR) {
                int t = idx >> 4, i = idx & 15;
                float gv = S->Qd[idx] * S->z[idx] + S->cd[idx];
                if (i < 12) gv += S->Yv[t * 12 + i];
                if (t < Td - 1) {
                    const float* Yn = &S->Yv[(t + 1) * 12];
                    float acc = 0.f;
                    #pragma unroll
                    for (int k = 0; k < 12; ++k) acc += S->M[k * 16 + i] * Yn[k];
                    gv -= acc;
                }
                if (i >= 12) {
                    int u = t * 4 + (i - 12);
                    float su = fmaxf(rho * (S->z[idx] - S->up[u]) + S->lamU[u], 0.f);
                    float sl = fmaxf(rho * (S->lo[u] - S->z[idx]) + S->lamL[u], 0.f);
                    gv += su - sl;
                    int a = (su > 0.f ? 1 : 0) | (sl > 0.f ? 2 : 0);
                    if (a != S->act[u]) {
                        S->act[u] = a;
                        atomicMin(&S->fmin, t);
                        atomicMax(&S->fmax, t);
                    }
                }
                S->g[idx] = gv;
            }
            __syncthreads();
            int fmn = (nt == 0) ? 0  : S->fmin;
            int fmx = (nt == 0) ? 31 : S->fmax;
            bool needFactor = (nt == 0) || (fmx >= 0);
            if (!needFactor) continue;   // unchanged active set: dz ~ roundoff

            {
                // ---- precompute diagonal blocks in the rebuild range ----
                for (int idx = tid; idx < 32 * 256; idx += NTHR) {
                    int t = idx >> 8;
                    bool rb = (t == 16) || (t <= 15 && t >= fmn) || (t >= 17 && t <= fmx);
                    if (rb) {
                        int e = idx & 255, i = e >> 4, c = e & 15;
                        S->D[t * MS + i * LS + c] = buildD(S, t, i, c, rho);
                    }
                }
                __syncthreads();

                int sstart = min(fmn, 31 - fmx);
                if (sstart < 0) sstart = 0;
                if (sstart > 15) sstart = 16;
                for (int s = sstart; s < 16; ++s) {
                    const int tf = s, tb = 31 - s;
                    const bool doF  = (tf >= fmn);
                    const bool doFU = doF && (tf > 0) && (tf - 1 >= fmn);
                    const bool doB  = (s < 15) && (fmx >= tb);
                    const bool doBU = doB && (fmx >= tb + 1);
                    // U builds (from previous rounds' in-place inverses)
                    for (int e = tid; e < 256; e += NTHR) {
                        int ri = e >> 4, rj = e & 15;
                        if (doFU) {
                            float v = 0.f;
                            if (ri < 12) {
                                const float* Pp = &S->D[(tf - 1) * MS];
                                const float* Mr = &S->M[ri * 16];
                                float a0 = 0.f, a1 = 0.f;
                                #pragma unroll
                                for (int m = 0; m < 16; m += 2) {
                                    a0 += Mr[m]     * Pp[m * LS + rj];
                                    a1 += Mr[m + 1] * Pp[(m + 1) * LS + rj];
                                }
                                v = rho * (a0 + a1);
                            }
                            S->Uf[tf * MS + ri * LS + rj] = v;
                        }
                        if (doBU) {
                            const float* Qp = &S->D[(tb + 1) * MS];
                            float a0 = 0.f, a1 = 0.f;
                            #pragma unroll
                            for (int m = 0; m < 12; m += 2) {
                                a0 += S->M[m * 16 + ri]       * Qp[m * LS + rj];
                                a1 += S->M[(m + 1) * 16 + ri] * Qp[(m + 1) * LS + rj];
                            }
                            S->Ub[tb * MS + ri * LS + rj] = rho * (a0 + a1);
                        }
                    }
                    __syncwarp();
                    // Schur corrections applied in place to D (row-local reads of U)
                    for (int e = tid; e < 256; e += NTHR) {
                        int ri = e >> 4, rj = e & 15;
                        if (doF && tf > 0 && ri < 12 && rj < 12) {
                            const float* Ur = &S->Uf[tf * MS + ri * LS];
                            const float* Mr = &S->M[rj * 16];
                            float a0 = 0.f, a1 = 0.f;
                            #pragma unroll
                            for (int k = 0; k < 16; k += 2) { a0 += Ur[k]*Mr[k]; a1 += Ur[k+1]*Mr[k+1]; }
                            S->D[tf * MS + ri * LS + rj] -= rho * (a0 + a1);
                        }
                        if (doB && s > 0) {
                            const float* Ur = &S->Ub[tb * MS + ri * LS];
                            float a0 = 0.f, a1 = 0.f;
                            #pragma unroll
                            for (int k = 0; k < 12; k += 2) {
                                a0 += Ur[k]     * S->M[k * 16 + rj];
                                a1 += Ur[k + 1] * S->M[(k + 1) * 16 + rj];
                            }
                            S->D[tb * MS + ri * LS + rj] -= rho * (a0 + a1);
                        }
                    }
                    __syncthreads();
                    if (wid == 0 && doF)      gj16b(&S->D[tf * MS], lane);
                    else if (wid == 1 && doB) gj16b(&S->D[tb * MS], lane);
                    __syncthreads();
                }
                // ---- middle block t=16 ----
                {
                    const bool doMUf = (fmn <= 15);
                    const bool doMUb = (fmx >= 17);
                    for (int e = tid; e < 256; e += NTHR) {
                        int ri = e >> 4, rj = e & 15;
                        if (doMUf) {
                            float v = 0.f;
                            if (ri < 12) {
                                const float* Pp = &S->D[15 * MS];
                                const float* Mr = &S->M[ri * 16];
                                float a0 = 0.f, a1 = 0.f;
                                #pragma unroll
                                for (int m = 0; m < 16; m += 2) {
                                    a0 += Mr[m] * Pp[m * LS + rj];
                                    a1 += Mr[m + 1] * Pp[(m + 1) * LS + rj];
                                }
                                v = rho * (a0 + a1);
                            }
                            S->Uf[16 * MS + ri * LS + rj] = v;
                        }
                        if (doMUb) {
                            const float* Qp = &S->D[17 * MS];
                            float a0 = 0.f, a1 = 0.f;
                            #pragma unroll
                            for (int m = 0; m < 12; m += 2) {
                                a0 += S->M[m * 16 + ri] * Qp[m * LS + rj];
                                a1 += S->M[(m + 1) * 16 + ri] * Qp[(m + 1) * LS + rj];
                            }
                            S->Ub[16 * MS + ri * LS + rj] = rho * (a0 + a1);
                        }
                    }
                    __syncwarp();
                    for (int e = tid; e < 256; e += NTHR) {
                        int ri = e >> 4, rj = e & 15;
                        float sub = 0.f;
                        if (ri < 12 && rj < 12) {
                            const float* Ur = &S->Uf[16 * MS + ri * LS];
                            const float* Mr = &S->M[rj * 16];
                            float a0 = 0.f;
                            #pragma unroll
                            for (int k = 0; k < 16; ++k) a0 += Ur[k] * Mr[k];
                            sub += rho * a0;
                        }
                        {
                            const float* Ur = &S->Ub[16 * MS + ri * LS];
                            float a0 = 0.f;
                            #pragma unroll
                            for (int k = 0; k < 12; ++k) a0 += Ur[k] * S->M[k * 16 + rj];
                            sub += rho * a0;
                        }
                        S->D[16 * MS + ri * LS + rj] -= sub;
                    }
                    __syncthreads();
                    if (wid == 0) gj16b(&S->D[16 * MS], lane);
                    __syncthreads();
                }
            }

            // ---- elimination sweeps (warp 0 fwd, warp 1 bwd, concurrent) ----
            if (wid == 0) {
                float w = (lane < 16) ? S->g[lane] : 0.f;
                for (int t = 1; t <= 15; ++t) {
                    float gv = (lane < 16) ? S->g[t * 16 + lane] : 0.f;
                    const float* Ur = &S->Uf[t * MS + (lane & 15) * LS];
                    float a0 = 0.f, a1 = 0.f;
                    #pragma unroll
                    for (int k = 0; k < 16; k += 2) {
                        a0 += Ur[k]     * __shfl_sync(0xffffffffu, w, k);
                        a1 += Ur[k + 1] * __shfl_sync(0xffffffffu, w, k + 1);
                    }
                    w = gv + a0 + a1;
                    if (lane < 16) S->g[t * 16 + lane] = w;
                }
            } else if (wid == 1) {
                float w = (lane < 16) ? S->g[31 * 16 + lane] : 0.f;
                for (int t = 30; t >= 17; --t) {
                    float gv = (lane < 16) ? S->g[t * 16 + lane] : 0.f;
                    const float* Ur = &S->Ub[t * MS + (lane & 15) * LS];
                    float a0 = 0.f, a1 = 0.f;
                    #pragma unroll
                    for (int k = 0; k < 16; k += 2) {
                        a0 += Ur[k]     * __shfl_sync(0xffffffffu, w, k);
                        a1 += Ur[k + 1] * __shfl_sync(0xffffffffu, w, k + 1);
                    }
                    w = gv + a0 + a1;
                    if (lane < 16) S->g[t * 16 + lane] = w;
                }
            }
            __syncthreads();
            // ---- middle rhs ----
            if (wid == 0 && lane < 16) {
                const float* Uf16 = &S->Uf[16 * MS + lane * LS];
                const float* Ub16 = &S->Ub[16 * MS + lane * LS];
                const float* w15  = &S->g[15 * 16];
                const float* w17  = &S->g[17 * 16];
                float acc = S->g[16 * 16 + lane];
                #pragma unroll
                for (int k = 0; k < 16; ++k) acc += Uf16[k] * w15[k] + Ub16[k] * w17[k];
                S->g[16 * 16 + lane] = acc;
            }
            __syncthreads();
            // ---- parallel: Pw_t = Dinv_t * w_t ----
            for (int idx = tid; idx < NZd; idx += NTHR) {
                int t = idx >> 4, i = idx & 15;
                const float* Pi = &S->D[t * MS + i * LS];
                const float* wv = &S->g[t * 16];
                float a0 = 0.f, a1 = 0.f;
                #pragma unroll
                for (int k = 0; k < 16; k += 2) { a0 += Pi[k] * wv[k]; a1 += Pi[k+1] * wv[k+1]; }
                S->Pw[idx] = a0 + a1;
            }
            __syncthreads();
            // ---- outward passes ----
            if (wid == 0) {
                float dz = (lane < 16) ? S->Pw[16 * 16 + lane] : 0.f;
                if (lane < 16) S->g[16 * 16 + lane] = dz;
                for (int t = 15; t >= 0; --t) {
                    float acc = (lane < 16) ? S->Pw[t * 16 + lane] : 0.f;
                    const float* Uc = &S->Uf[(t + 1) * MS];
                    #pragma unroll
                    for (int k = 0; k < 12; ++k)
                        acc += Uc[k * LS + (lane & 15)] * __shfl_sync(0xffffffffu, dz, k);
                    dz = acc;
                    if (lane < 16) S->g[t * 16 + lane] = dz;
                }
            } else if (wid == 1) {
                float dz = (lane < 16) ? S->Pw[16 * 16 + lane] : 0.f;
                for (int t = 17; t <= 31; ++t) {
                    float acc = (lane < 16) ? S->Pw[t * 16 + lane] : 0.f;
                    const float* Uc = &S->Ub[(t - 1) * MS];
                    #pragma unroll
                    for (int k = 0; k < 16; ++k)
                        acc += Uc[k * LS + (lane & 15)] * __shfl_sync(0xffffffffu, dz, k);
                    dz = acc;
                    if (lane < 16) S->g[t * 16 + lane] = dz;
                }
            }
            __syncthreads();
            // ---- z -= dz ----
            for (int idx = tid; idx < NZd; idx += NTHR) S->z[idx] -= S->g[idx];
            __syncthreads();
        } // newton

        // ---- multiplier updates ----
        for (int idx = tid; idx < NEQ; idx += NTHR) {
            int t = idx / 12, i = idx % 12;
            float r;
            if (t == 0) r = S->z[i] - S->x0[i];
            else {
                float acc = S->z[t * 16 + i];
                const float* zp = &S->z[(t - 1) * 16];
                const float* Mr = &S->M[i * 16];
                #pragma unroll
                for (int k = 0; k < 16; ++k) acc -= Mr[k] * zp[k];
                r = acc;
            }
            S->lamE[idx] += rho * r;
        }
        for (int idx = tid; idx < NIN; idx += NTHR) {
            int t = idx >> 2, j = idx & 3;
            float uv = S->z[t * 16 + 12 + j];
            S->lamU[idx] = fmaxf(S->lamU[idx] + rho * (uv - S->up[idx]), 0.f);
            S->lamL[idx] = fmaxf(S->lamL[idx] + rho * (S->lo[idx] - uv), 0.f);
        }
        __syncthreads();
        rho = fminf(rho * 10.f, 100.f);
    } // al

    // ---------------- outputs: x [NB,T,NS] then u [NB,T,NC] ----------------
    for (int idx = tid; idx < NEQ; idx += NTHR) {
        int t = idx / 12, i = idx % 12;
        out[b * (Td * NSd) + idx] = S->z[t * 16 + i];
    }
    for (int idx = tid; idx < NIN; idx += NTHR) {
        int t = idx >> 2, j = idx & 3;
        out[NB * (Td * NSd) + b * (Td * NCd) + idx] = S->z[t * 16 + 12 + j];
    }
}

extern "C" void kernel_launch(void* const* d_in, const int* in_sizes, int n_in,
                              void* d_out, int out_size)
{
    const float* x0 = (const float*)d_in[0];
    const float* Q  = (const float*)d_in[1];
    const float* c  = (const float*)d_in[2];
    const float* A  = (const float*)d_in[3];
    const float* B  = (const float*)d_in[4];
    const float* lo = (const float*)d_in[5];
    const float* up = (const float*)d_in[6];
    float* out = (float*)d_out;

    int NB = in_sizes[0] / NSd;   // 64
    size_t smem = sizeof(Smem);
    cudaFuncSetAttribute(mpc_kernel, cudaFuncAttributeMaxDynamicSharedMemorySize, (int)smem);
    mpc_kernel<<<NB, NTHR, smem>>>(x0, Q, c, A, B, lo, up, out, NB);
}

// round 16
// speedup vs baseline: 1.2613x; 1.0888x over previous
#include <cuda_runtime.h>
#include <math.h>

#define NSd   12
#define NCd   4
#define Td    32
#define NZd   512          // T * 16
#define NEQ   384
#define NIN   128
#define DAMPv 1e-4f
#define LS    17           // padded row stride
#define NTHR  128

struct Smem {
    float M[256];             // [A|B] row-major, 12x16 (rows 12-15 zero)
    float MtM[256];
    float x0[12];
    float z[NZd], Qd[NZd], cd[NZd], g[NZd], Pw[NZd];
    float lamE[NEQ], lamU[NIN], lamL[NIN], lo[NIN], up[NIN];
    float Yv[NEQ];
    float Pa[16 * LS], Pb[16 * LS];
    float inv[32 * 16 * LS];  // t<=16: Pinv (fwd);  t>=17: Qbinv (bwd)
    float Uf[17 * 16 * LS];   // Uf[t] = rho*M*Pinv_{t-1}, rows>=12 zero
    float Ub[31 * 16 * LS];   // Ub[t] = rho*M^T*S*Qbinv_{t+1}, full
    int   act[NIN];
    int   fmin, fmax;
};

__device__ __forceinline__ float buildD(const Smem* S, int t, int i, int j, float rho) {
    float v = (t < Td - 1) ? rho * S->MtM[i * 16 + j] : 0.f;
    if (i == j) {
        v += S->Qd[t * 16 + i] + DAMPv;
        if (i < 12) v += rho;
        else {
            int a = S->act[t * 4 + (i - 12)];
            if (a & 1) v += rho;
            if (a & 2) v += rho;
        }
    }
    return v;
}

// split-lane branch-free Gauss-Jordan with 2x2 BLOCK pivots (8 serial steps).
// lane = (row r, col-half h); each lane owns 8 columns of its row.
__device__ __forceinline__ void gj16b(const float* Psrc, float* dst, int lane) {
    const int r  = lane & 15;
    const int h  = (lane >> 4) & 1;
    const int c0 = h << 3;
    float a[8];
    #pragma unroll
    for (int j = 0; j < 8; ++j) a[j] = Psrc[r * LS + c0 + j];
    #pragma unroll
    for (int kb = 0; kb < 8; ++kb) {
        const int p  = 2 * kb, q = p + 1;
        const int kh = p >> 3;            // both p,q in same half (p even)
        const int pc = p & 7, qc = q & 7;
        // 2x2 pivot block (old values)
        float bpp = __shfl_sync(0xffffffffu, a[pc], p + (kh << 4));
        float bpq = __shfl_sync(0xffffffffu, a[qc], p + (kh << 4));
        float bqp = __shfl_sync(0xffffffffu, a[pc], q + (kh << 4));
        float bqq = __shfl_sync(0xffffffffu, a[qc], q + (kh << 4));
        float idet = __fdividef(1.0f, bpp * bqq - bpq * bqp);
        float i00 =  bqq * idet, i01 = -bpq * idet;
        float i10 = -bqp * idet, i11 =  bpp * idet;
        // this lane's row factor F = (a[r][p], a[r][q]); G = F * Binv
        float f0 = __shfl_sync(0xffffffffu, a[pc], r + (kh << 4));
        float f1 = __shfl_sync(0xffffffffu, a[qc], r + (kh << 4));
        float g0 = f0 * i00 + f1 * i10;
        float g1 = f0 * i01 + f1 * i11;
        const bool isp = (r == p), isq = (r == q);
        #pragma unroll
        for (int j = 0; j < 8; ++j) {
            float R0 = __shfl_sync(0xffffffffu, a[j], p + (h << 4));  // old pivot rows
            float R1 = __shfl_sync(0xffffffffu, a[j], q + (h << 4));
            float np  = i00 * R0 + i01 * R1;     // new row p
            float nq  = i10 * R0 + i11 * R1;     // new row q
            float upd = a[j] - g0 * R0 - g1 * R1;
            a[j] = isp ? np : (isq ? nq : upd);
        }
        // pivot-block column fixup
        if (h == kh) {
            a[pc] = isp ? i00 : (isq ? i10 : -g0);
            a[qc] = isp ? i01 : (isq ? i11 : -g1);
        }
    }
    #pragma unroll
    for (int j = 0; j < 8; ++j) dst[r * LS + c0 + j] = a[j];
}

__global__ __launch_bounds__(NTHR, 1)
void mpc_kernel(const float* __restrict__ x0g, const float* __restrict__ Qg,
                const float* __restrict__ cg,  const float* __restrict__ Ag,
                const float* __restrict__ Bg,  const float* __restrict__ log_,
                const float* __restrict__ upg, float* __restrict__ out, int NB)
{
    extern __shared__ float smraw[];
    Smem* S = reinterpret_cast<Smem*>(smraw);
    const int b    = blockIdx.x;
    const int tid  = threadIdx.x;
    const int wid  = tid >> 5;
    const int lane = tid & 31;

    // ---------------- load inputs ----------------
    for (int i = tid; i < NZd; i += NTHR) {
        S->z[i]  = 0.f;
        S->Qd[i] = Qg[b * NZd + i];
        S->cd[i] = cg[b * NZd + i];
    }
    for (int i = tid; i < NEQ; i += NTHR) S->lamE[i] = 0.f;
    for (int i = tid; i < NIN; i += NTHR) {
        S->lamU[i] = 0.f; S->lamL[i] = 0.f;
        S->lo[i]  = log_[b * NIN + i];
        S->up[i]  = upg[b * NIN + i];
        S->act[i] = -1;
    }
    for (int i = tid; i < 256; i += NTHR) {
        int r = i >> 4, cc = i & 15;
        float mv = 0.f;
        if (r < 12) mv = (cc < 12) ? Ag[r * 12 + cc] : Bg[r * 4 + (cc - 12)];
        S->M[i] = mv;
    }
    if (tid < 12) S->x0[tid] = x0g[b * 12 + tid];
    __syncthreads();

    // ---------------- MtM ----------------
    for (int e = tid; e < 256; e += NTHR) {
        int ri = e >> 4, rj = e & 15;
        float a = 0.f;
        #pragma unroll
        for (int k = 0; k < 12; ++k) a += S->M[k * 16 + ri] * S->M[k * 16 + rj];
        S->MtM[e] = a;
    }

    // ---------------- initial rollout (warp 0) ----------------
    if (tid < 32) {
        if (tid < 12) S->z[tid] = S->x0[tid];
        for (int t = 0; t < Td - 1; ++t) {
            __syncwarp();
            if (tid < 12) {
                float acc = 0.f;
                #pragma unroll
                for (int j = 0; j < 12; ++j) acc += S->M[tid * 16 + j] * S->z[t * 16 + j];
                S->z[(t + 1) * 16 + tid] = acc;
            }
        }
    }
    __syncthreads();

    float rho = 1.f;
    for (int al = 0; al < 3; ++al) {
        for (int nt = 0; nt < 3; ++nt) {
            // ---- Yv = rho*r + lamE ----
            if (tid == 0) { S->fmin = 32; S->fmax = -1; }
            for (int idx = tid; idx < NEQ; idx += NTHR) {
                int t = idx / 12, i = idx % 12;
                float r;
                if (t == 0) r = S->z[i] - S->x0[i];
                else {
                    float acc = S->z[t * 16 + i];
                    const float* zp = &S->z[(t - 1) * 16];
                    const float* Mr = &S->M[i * 16];
                    #pragma unroll
                    for (int k = 0; k < 16; ++k) acc -= Mr[k] * zp[k];
                    r = acc;
                }
                S->Yv[idx] = rho * r + S->lamE[idx];
            }
            __syncthreads();
            // ---- gradient + active-set flip tracking ----
            for (int idx = tid; idx < NZd; idx += NTHR) {
                int t = idx >> 4, i = idx & 15;
                float gv = S->Qd[idx] * S->z[idx] + S->cd[idx];
                if (i < 12) gv += S->Yv[t * 12 + i];
                if (t < Td - 1) {
                    const float* Yn = &S->Yv[(t + 1) * 12];
                    float acc = 0.f;
                    #pragma unroll
                    for (int k = 0; k < 12; ++k) acc += S->M[k * 16 + i] * Yn[k];
                    gv -= acc;
                }
                if (i >= 12) {
                    int u = t * 4 + (i - 12);
                    float su = fmaxf(rho * (S->z[idx] - S->up[u]) + S->lamU[u], 0.f);
                    float sl = fmaxf(rho * (S->lo[u] - S->z[idx]) + S->lamL[u], 0.f);
                    gv += su - sl;
                    int a = (su > 0.f ? 1 : 0) | (sl > 0.f ? 2 : 0);
                    if (a != S->act[u]) {
                        S->act[u] = a;
                        atomicMin(&S->fmin, t);
                        atomicMax(&S->fmax, t);
                    }
                }
                S->g[idx] = gv;
            }
            __syncthreads();
            int fmn = (nt == 0) ? 0  : S->fmin;
            int fmx = (nt == 0) ? 31 : S->fmax;
            bool needFactor = (nt == 0) || (fmx >= 0);

            // Active set unchanged (nt>0): previous Newton step already minimized
            // this quadratic piece -> dz ~ roundoff. Skip the whole solve.
            if (!needFactor) continue;

            {
                int sstart = min(fmn, 31 - fmx);
                if (sstart < 0) sstart = 0;
                if (sstart > 15) sstart = 16;
                for (int s = sstart; s < 16; ++s) {
                    const int tf = s, tb = 31 - s;
                    const bool doF  = (tf >= fmn);
                    const bool doFU = doF && (tf > 0) && (tf - 1 >= fmn);
                    const bool doB  = (s < 15) && (fmx >= tb);
                    const bool doBU = doB && (fmx >= tb + 1);
                    // U builds
                    for (int e = tid; e < 256; e += NTHR) {
                        int ri = e >> 4, rj = e & 15;
                        if (doFU) {
                            float v = 0.f;
                            if (ri < 12) {
                                const float* Pp = &S->inv[(tf - 1) * 16 * LS];
                                const float* Mr = &S->M[ri * 16];
                                float a0 = 0.f, a1 = 0.f;
                                #pragma unroll
                                for (int m = 0; m < 16; m += 2) {
                                    a0 += Mr[m]     * Pp[m * LS + rj];
                                    a1 += Mr[m + 1] * Pp[(m + 1) * LS + rj];
                                }
                                v = rho * (a0 + a1);
                            }
                            S->Uf[tf * 16 * LS + ri * LS + rj] = v;
                        }
                        if (doBU) {
                            const float* Qp = &S->inv[(tb + 1) * 16 * LS];
                            float a0 = 0.f, a1 = 0.f;
                            #pragma unroll
                            for (int m = 0; m < 12; m += 2) {
                                a0 += S->M[m * 16 + ri]       * Qp[m * LS + rj];
                                a1 += S->M[(m + 1) * 16 + ri] * Qp[(m + 1) * LS + rj];
                            }
                            S->Ub[tb * 16 * LS + ri * LS + rj] = rho * (a0 + a1);
                        }
                    }
                    __syncwarp();
                    // P builds
                    for (int e = tid; e < 256; e += NTHR) {
                        int ri = e >> 4, rj = e & 15;
                        if (doF) {
                            float v = buildD(S, tf, ri, rj, rho);
                            if (tf > 0 && ri < 12 && rj < 12) {
                                const float* Ur = &S->Uf[tf * 16 * LS + ri * LS];
                                const float* Mr = &S->M[rj * 16];
                                float a0 = 0.f, a1 = 0.f;
                                #pragma unroll
                                for (int k = 0; k < 16; k += 2) { a0 += Ur[k] * Mr[k]; a1 += Ur[k+1] * Mr[k+1]; }
                                v -= rho * (a0 + a1);
                            }
                            S->Pa[ri * LS + rj] = v;
                        }
                        if (doB) {
                            float v = buildD(S, tb, ri, rj, rho);
                            if (s > 0) {
                                const float* Ur = &S->Ub[tb * 16 * LS + ri * LS];
                                float a0 = 0.f, a1 = 0.f;
                                #pragma unroll
                                for (int k = 0; k < 12; k += 2) {
                                    a0 += Ur[k]     * S->M[k * 16 + rj];
                                    a1 += Ur[k + 1] * S->M[(k + 1) * 16 + rj];
                                }
                                v -= rho * (a0 + a1);
                            }
                            S->Pb[ri * LS + rj] = v;
                        }
                    }
                    __syncthreads();
                    // concurrent inversions: one matrix per warp (separate SMSPs)
                    if (wid == 0 && doF)      gj16b(S->Pa, &S->inv[tf * 16 * LS], lane);
                    else if (wid == 1 && doB) gj16b(S->Pb, &S->inv[tb * 16 * LS], lane);
                    __syncthreads();
                }
                // ---- middle block t=16 ----
                {
                    const bool doMUf = (fmn <= 15);
                    const bool doMUb = (fmx >= 17);
                    for (int e = tid; e < 256; e += NTHR) {
                        int ri = e >> 4, rj = e & 15;
                        if (doMUf) {
                            float v = 0.f;
                            if (ri < 12) {
                                const float* Pp = &S->inv[15 * 16 * LS];
                                const float* Mr = &S->M[ri * 16];
                                float a0 = 0.f, a1 = 0.f;
                                #pragma unroll
                                for (int m = 0; m < 16; m += 2) {
                                    a0 += Mr[m] * Pp[m * LS + rj];
                                    a1 += Mr[m + 1] * Pp[(m + 1) * LS + rj];
                                }
                                v = rho * (a0 + a1);
                            }
                            S->Uf[16 * 16 * LS + ri * LS + rj] = v;
                        }
                        if (doMUb) {
                            const float* Qp = &S->inv[17 * 16 * LS];
                            float a0 = 0.f, a1 = 0.f;
                            #pragma unroll
                            for (int m = 0; m < 12; m += 2) {
                                a0 += S->M[m * 16 + ri] * Qp[m * LS + rj];
                                a1 += S->M[(m + 1) * 16 + ri] * Qp[(m + 1) * LS + rj];
                            }
                            S->Ub[16 * 16 * LS + ri * LS + rj] = rho * (a0 + a1);
                        }
                    }
                    __syncwarp();
                    for (int e = tid; e < 256; e += NTHR) {
                        int ri = e >> 4, rj = e & 15;
                        float pv = buildD(S, 16, ri, rj, rho);
                        if (ri < 12 && rj < 12) {
                            const float* Ur = &S->Uf[16 * 16 * LS + ri * LS];
                            const float* Mr = &S->M[rj * 16];
                            float a0 = 0.f;
                            #pragma unroll
                            for (int k = 0; k < 16; ++k) a0 += Ur[k] * Mr[k];
                            pv -= rho * a0;
                        }
                        {
                            const float* Ur = &S->Ub[16 * 16 * LS + ri * LS];
                            float a0 = 0.f;
                            #pragma unroll
                            for (int k = 0; k < 12; ++k) a0 += Ur[k] * S->M[k * 16 + rj];
                            pv -= rho * a0;
                        }
                        S->Pa[ri * LS + rj] = pv;
                    }
                    __syncthreads();
                    if (wid == 0) gj16b(S->Pa, &S->inv[16 * 16 * LS], lane);
                    __syncthreads();
                }
            }

            // ---- elimination sweeps (warp 0 fwd, warp 1 bwd, concurrent) ----
            if (wid == 0) {
                float w = (lane < 16) ? S->g[lane] : 0.f;
                for (int t = 1; t <= 15; ++t) {
                    float gv = (lane < 16) ? S->g[t * 16 + lane] : 0.f;
                    const float* Ur = &S->Uf[t * 16 * LS + (lane & 15) * LS];
                    float a0 = 0.f, a1 = 0.f;
                    #pragma unroll
                    for (int k = 0; k < 16; k += 2) {
                        a0 += Ur[k]     * __shfl_sync(0xffffffffu, w, k);
                        a1 += Ur[k + 1] * __shfl_sync(0xffffffffu, w, k + 1);
                    }
                    w = gv + a0 + a1;
                    if (lane < 16) S->g[t * 16 + lane] = w;
                }
            } else if (wid == 1) {
                float w = (lane < 16) ? S->g[31 * 16 + lane] : 0.f;
                for (int t = 30; t >= 17; --t) {
                    float gv = (lane < 16) ? S->g[t * 16 + lane] : 0.f;
                    const float* Ur = &S->Ub[t * 16 * LS + (lane & 15) * LS];
                    float a0 = 0.f, a1 = 0.f;
                    #pragma unroll
                    for (int k = 0; k < 16; k += 2) {
                        a0 += Ur[k]     * __shfl_sync(0xffffffffu, w, k);
                        a1 += Ur[k + 1] * __shfl_sync(0xffffffffu, w, k + 1);
                    }
                    w = gv + a0 + a1;
                    if (lane < 16) S->g[t * 16 + lane] = w;
                }
            }
            __syncthreads();
            // ---- middle rhs ----
            if (wid == 0 && lane < 16) {
                const float* Uf16 = &S->Uf[16 * 16 * LS + lane * LS];
                const float* Ub16 = &S->Ub[16 * 16 * LS + lane * LS];
                const float* w15  = &S->g[15 * 16];
                const float* w17  = &S->g[17 * 16];
                float acc = S->g[16 * 16 + lane];
                #pragma unroll
                for (int k = 0; k < 16; ++k) acc += Uf16[k] * w15[k] + Ub16[k] * w17[k];
                S->g[16 * 16 + lane] = acc;
            }
            __syncthreads();
            // ---- parallel: Pw_t = inv_t * w_t ----
            for (int idx = tid; idx < NZd; idx += NTHR) {
                int t = idx >> 4, i = idx & 15;
                const float* Pi = &S->inv[t * 16 * LS + i * LS];
                const float* wv = &S->g[t * 16];
                float a0 = 0.f, a1 = 0.f;
                #pragma unroll
                for (int k = 0; k < 16; k += 2) { a0 += Pi[k] * wv[k]; a1 += Pi[k+1] * wv[k+1]; }
                S->Pw[idx] = a0 + a1;
            }
            __syncthreads();
            // ---- outward passes ----
            if (wid == 0) {
                float dz = (lane < 16) ? S->Pw[16 * 16 + lane] : 0.f;
                if (lane < 16) S->g[16 * 16 + lane] = dz;
                for (int t = 15; t >= 0; --t) {
                    float acc = (lane < 16) ? S->Pw[t * 16 + lane] : 0.f;
                    const float* Uc = &S->Uf[(t + 1) * 16 * LS];
                    #pragma unroll
                    for (int k = 0; k < 12; ++k)
                        acc += Uc[k * LS + (lane & 15)] * __shfl_sync(0xffffffffu, dz, k);
                    dz = acc;
                    if (lane < 16) S->g[t * 16 + lane] = dz;
                }
            } else if (wid == 1) {
                float dz = (lane < 16) ? S->Pw[16 * 16 + lane] : 0.f;
                for (int t = 17; t <= 31; ++t) {
                    float acc = (lane < 16) ? S->Pw[t * 16 + lane] : 0.f;
                    const float* Uc = &S->Ub[(t - 1) * 16 * LS];
                    #pragma unroll
                    for (int k = 0; k < 16; ++k)
                        acc += Uc[k * LS + (lane & 15)] * __shfl_sync(0xffffffffu, dz, k);
                    dz = acc;
                    if (lane < 16) S->g[t * 16 + lane] = dz;
                }
            }
            __syncthreads();
            // ---- z -= dz ----
            for (int idx = tid; idx < NZd; idx += NTHR) S->z[idx] -= S->g[idx];
            __syncthreads();
        } // newton

        // ---- multiplier updates ----
        for (int idx = tid; idx < NEQ; idx += NTHR) {
            int t = idx / 12, i = idx % 12;
            float r;
            if (t == 0) r = S->z[i] - S->x0[i];
            else {
                float acc = S->z[t * 16 + i];
                const float* zp = &S->z[(t - 1) * 16];
                const float* Mr = &S->M[i * 16];
                #pragma unroll
                for (int k = 0; k < 16; ++k) acc -= Mr[k] * zp[k];
                r = acc;
            }
            S->lamE[idx] += rho * r;
        }
        for (int idx = tid; idx < NIN; idx += NTHR) {
            int t = idx >> 2, j = idx & 3;
            float uv = S->z[t * 16 + 12 + j];
            S->lamU[idx] = fmaxf(S->lamU[idx] + rho * (uv - S->up[idx]), 0.f);
            S->lamL[idx] = fmaxf(S->lamL[idx] + rho * (S->lo[idx] - uv), 0.f);
        }
        __syncthreads();
        rho = fminf(rho * 10.f, 100.f);
    } // al

    // ---------------- outputs: x [NB,T,NS] then u [NB,T,NC] ----------------
    for (int idx = tid; idx < NEQ; idx += NTHR) {
        int t = idx / 12, i = idx % 12;
        out[b * (Td * NSd) + idx] = S->z[t * 16 + i];
    }
    for (int idx = tid; idx < NIN; idx += NTHR) {
        int t = idx >> 2, j = idx & 3;
        out[NB * (Td * NSd) + b * (Td * NCd) + idx] = S->z[t * 16 + 12 + j];
    }
}

extern "C" void kernel_launch(void* const* d_in, const int* in_sizes, int n_in,
                              void* d_out, int out_size)
{
    const float* x0 = (const float*)d_in[0];
    const float* Q  = (const float*)d_in[1];
    const float* c  = (const float*)d_in[2];
    const float* A  = (const float*)d_in[3];
    const float* B  = (const float*)d_in[4];
    const float* lo = (const float*)d_in[5];
    const float* up = (const float*)d_in[6];
    float* out = (float*)d_out;

    int NB = in_sizes[0] / NSd;   // 64
    size_t smem = sizeof(Smem);
    cudaFuncSetAttribute(mpc_kernel, cudaFuncAttributeMaxDynamicSharedMemorySize, (int)smem);
    mpc_kernel<<<NB, NTHR, smem>>>(x0, Q, c, A, B, lo, up, out, NB);
}